// round 14
// baseline (speedup 1.0000x reference)
#include <cuda_runtime.h>
#include <cuda_fp16.h>
#include <cstdint>

// Problem constants
#define BB   2
#define SS   2048
#define DD   1024
#define HH   16
#define DK   64
#define N3   3072   // 3*D
#define NTOK 4096   // B*S

// Scratch (allocation-free rule: __device__ globals) — all fp16 MMA operands
__device__ __half g_qh[BB * HH * SS * DK];   // [bh, s, dk]
__device__ __half g_kh[BB * HH * SS * DK];
__device__ __half g_vh[BB * HH * SS * DK];
__device__ __half g_oh[NTOK * DD];           // [token, h*64+d]
__device__ __half g_xh[NTOK * DD];           // x -> fp16
__device__ __half g_wqkvh[N3 * DD];          // w_qkv -> fp16
__device__ __half g_woh[DD * DD];            // w_o -> fp16

// ---------------------------------------------------------------------------
// PTX helpers — base sm_80+ ISA only (harness targets plain sm_103: NO tcgen05)
// ---------------------------------------------------------------------------
__device__ __forceinline__ uint32_t smem_u32(const void* p) {
    uint32_t a;
    asm("{ .reg .u64 t; cvta.to.shared.u64 t, %1; cvt.u32.u64 %0, t; }"
        : "=r"(a) : "l"(p));
    return a;
}

#define CP16(dst, src) \
    asm volatile("cp.async.cg.shared.global [%0], [%1], 16;" :: "r"(dst), "l"(src))
#define CP_COMMIT() asm volatile("cp.async.commit_group;" ::: "memory")
#define CP_WAIT(n)  asm volatile("cp.async.wait_group %0;" :: "n"(n) : "memory")

__device__ __forceinline__ void ldsm4(uint32_t* r, uint32_t addr) {
    asm volatile("ldmatrix.sync.aligned.m8n8.x4.shared.b16 {%0,%1,%2,%3}, [%4];"
        : "=r"(r[0]), "=r"(r[1]), "=r"(r[2]), "=r"(r[3]) : "r"(addr));
}
__device__ __forceinline__ void ldsm4t(uint32_t* r, uint32_t addr) {
    asm volatile("ldmatrix.sync.aligned.m8n8.x4.trans.shared.b16 {%0,%1,%2,%3}, [%4];"
        : "=r"(r[0]), "=r"(r[1]), "=r"(r[2]), "=r"(r[3]) : "r"(addr));
}

__device__ __forceinline__ void mma_f16(float* c, const uint32_t* a,
                                        uint32_t b0, uint32_t b1) {
    asm volatile(
        "mma.sync.aligned.m16n8k16.row.col.f32.f16.f16.f32 "
        "{%0,%1,%2,%3}, {%4,%5,%6,%7}, {%8,%9}, {%0,%1,%2,%3};"
        : "+f"(c[0]), "+f"(c[1]), "+f"(c[2]), "+f"(c[3])
        : "r"(a[0]), "r"(a[1]), "r"(a[2]), "r"(a[3]), "r"(b0), "r"(b1));
}

__device__ __forceinline__ float ex2(float x) {
    float r;
    asm("ex2.approx.f32 %0, %1;" : "=f"(r) : "f"(x));
    return r;
}
__device__ __forceinline__ uint32_t pack_h2(float a, float b) {
    __half2 h = __floats2half2_rn(a, b);
    return *(uint32_t*)&h;
}

// ---------------------------------------------------------------------------
// Kernel 0: fused fp32 -> fp16 convert for x, w_qkv, w_o (one launch)
// ---------------------------------------------------------------------------
#define XB  (NTOK * DD / 1024)
#define WB  (N3 * DD / 1024)
#define OB  (DD * DD / 1024)

__global__ __launch_bounds__(256) void to_half_all(
    const float* __restrict__ x, const float* __restrict__ wqkv,
    const float* __restrict__ wo)
{
    int b = blockIdx.x;
    const float* src;  __half2* dst;
    if (b < XB)            { src = x;    dst = (__half2*)g_xh; }
    else if (b < XB + WB)  { src = wqkv; dst = (__half2*)g_wqkvh; b -= XB; }
    else                   { src = wo;   dst = (__half2*)g_woh;   b -= XB + WB; }
    const int i = b * 256 + threadIdx.x;
    float4 v = *(const float4*)(src + i * 4);
    dst[i * 2]     = __floats2half2_rn(v.x, v.y);
    dst[i * 2 + 1] = __floats2half2_rn(v.z, v.w);
}

// ---------------------------------------------------------------------------
// fp16 mma.sync GEMM: block tile 128x256, 8 warps (warp tile 64x64),
// 2-stage cp.async (48KB/stage), 1 CTA/SM.
// MODE 0: A = g_xh, B = g_wqkvh; epilogue scatters fp16 Q/K/V.
// MODE 1: A = g_oh, B = g_woh;   epilogue writes final fp32 Out + bias.
// ---------------------------------------------------------------------------
#define GSTAGE_BYTES 49152          // A 128x128B (16KB) + B 256x128B (32KB)
#define NCHUNK       16             // K=1024 / 64
#define GEMM_SMEM    (1024 + 2 * GSTAGE_BYTES)

template<int MODE>
__global__ __launch_bounds__(256, 1) void gemm_mma(
    const float* __restrict__ bias, float* __restrict__ Out)
{
    extern __shared__ __align__(16) char smem_raw[];
    const uint32_t sb  = smem_u32(smem_raw);
    const uint32_t st0 = (sb + 1023u) & ~1023u;

    const int t    = threadIdx.x;
    const int lane = t & 31;
    const int wid  = t >> 5;
    const int wm   = wid & 1;          // 2 warp rows  (64 m each)
    const int wn   = wid >> 1;         // 4 warp cols  (64 n each)
    const int m0   = blockIdx.y * 128;
    const int n0   = blockIdx.x * 256;

    const __half* A  = (MODE == 1) ? g_oh : g_xh;
    const __half* Bw = (MODE == 1) ? g_woh : g_wqkvh;

    // ---- cp.async: 12 x 16B per thread per chunk (A 4, B 8) ---------------
    const int rb = t >> 3;            // base row 0..31
    const int q  = t & 7;             // 16B quad within 128B row
    const __half* Abase = A  + (size_t)m0 * DD + q * 8;
    const __half* Bbase = Bw + (size_t)n0 * DD + q * 8;

    auto load_chunk = [&](int c) {
        const uint32_t st = st0 + (c & 1) * GSTAGE_BYTES;
        const __half* Ac = Abase + c * 64;
        const __half* Bc = Bbase + c * 64;
#pragma unroll
        for (int it = 0; it < 4; it++) {
            int r = rb + it * 32;
            CP16(st + r * 128 + ((q ^ (r & 7)) << 4), Ac + (size_t)r * DD);
        }
#pragma unroll
        for (int it = 0; it < 8; it++) {
            int r = rb + it * 32;
            CP16(st + 16384 + r * 128 + ((q ^ (r & 7)) << 4), Bc + (size_t)r * DD);
        }
    };

    // ---- ldmatrix geometry (m16n8k16) -------------------------------------
    const int rx = lane & 7;
    const int r8 = ((lane >> 3) & 1) * 8;
    const int qh = (lane >> 4) & 1;
    const int rB8 = ((lane >> 4) & 1) * 8;
    const int qB  = (lane >> 3) & 1;

    float acc[4][8][4];
#pragma unroll
    for (int mt = 0; mt < 4; mt++)
#pragma unroll
        for (int nt = 0; nt < 8; nt++)
#pragma unroll
            for (int i = 0; i < 4; i++) acc[mt][nt][i] = 0.0f;

    load_chunk(0); CP_COMMIT();

    for (int c = 0; c < NCHUNK; c++) {
        CP_WAIT(0);
        __syncthreads();
        if (c + 1 < NCHUNK) { load_chunk(c + 1); CP_COMMIT(); }

        const uint32_t stA = st0 + (c & 1) * GSTAGE_BYTES;
        const uint32_t stB = stA + 16384;
#pragma unroll
        for (int ks = 0; ks < 4; ks++) {      // k16 steps within 64-half chunk
            uint32_t a[4][4], b[4][4];
            const uint32_t aph = ((2 * ks + qh) ^ rx) << 4;
            const uint32_t bph = ((2 * ks + qB) ^ rx) << 4;
#pragma unroll
            for (int mt = 0; mt < 4; mt++)
                ldsm4(a[mt], stA + (wm * 64 + mt * 16 + r8 + rx) * 128 + aph);
#pragma unroll
            for (int p = 0; p < 4; p++)
                ldsm4(b[p], stB + (wn * 64 + p * 16 + rB8 + rx) * 128 + bph);
#pragma unroll
            for (int mt = 0; mt < 4; mt++)
#pragma unroll
                for (int nt = 0; nt < 8; nt++)
                    mma_f16(acc[mt][nt], a[mt],
                            b[nt >> 1][(nt & 1) * 2],
                            b[nt >> 1][(nt & 1) * 2 + 1]);
        }
    }

    // ---- epilogue ---------------------------------------------------------
    const int g  = lane >> 2;
    const int t4 = lane & 3;
#pragma unroll
    for (int mt = 0; mt < 4; mt++) {
        const int m = m0 + wm * 64 + mt * 16 + g;
#pragma unroll
        for (int nt = 0; nt < 8; nt++) {
            const int n = n0 + wn * 64 + nt * 8 + 2 * t4;
            const float2 b2 = *(const float2*)&bias[n];
            float2 v0, v1;
            v0.x = acc[mt][nt][0] + b2.x; v0.y = acc[mt][nt][1] + b2.y;
            v1.x = acc[mt][nt][2] + b2.x; v1.y = acc[mt][nt][3] + b2.y;
            if (MODE == 1) {
                *(float2*)&Out[(size_t)m * DD + n]       = v0;
                *(float2*)&Out[(size_t)(m + 8) * DD + n] = v1;
            } else {
                const __half2 h0 = __floats2half2_rn(v0.x, v0.y);
                const __half2 h1 = __floats2half2_rn(v1.x, v1.y);
                const int sel = n >> 10;
                const int h   = (n & 1023) >> 6;
                const int dk  = n & 63;
                __half* dst = (sel == 0) ? g_qh : ((sel == 1) ? g_kh : g_vh);
                const int b0i = m >> 11, s0 = m & 2047;
                *(__half2*)&dst[((size_t)(b0i * HH + h) * SS + s0) * DK + dk] = h0;
                const int b1i = (m + 8) >> 11, s1 = (m + 8) & 2047;
                *(__half2*)&dst[((size_t)(b1i * HH + h) * SS + s1) * DK + dk] = h1;
            }
        }
    }
}

// ---------------------------------------------------------------------------
// Kernel 2: flash attention, fp16 mma.sync, P in registers, exp2 softmax.
// (proven round-10 version, unchanged)
// ---------------------------------------------------------------------------
#define FBM 128
#define FBN 64
#define QS_OFF  0
#define KS_OFF  16384
#define VS_OFF  32768
#define FLASH_SMEM 49152

__global__ __launch_bounds__(256) void flash_mma_kernel()
{
    extern __shared__ __align__(16) char sm[];
    const uint32_t S0 = smem_u32(sm);

    const int t    = threadIdx.x;
    const int lane = t & 31;
    const int w    = t >> 5;
    const int bh   = blockIdx.y;
    const int qt   = (int)gridDim.x - 1 - (int)blockIdx.x;   // heavy first
    const int q0   = qt * FBM;

    const __half* Qg = g_qh + (size_t)(bh * SS + q0) * DK;
    const __half* Kg = g_kh + (size_t)bh * SS * DK;
    const __half* Vg = g_vh + (size_t)bh * SS * DK;

    const int ntiles = q0 / FBN + 2;

    {
        int r = t >> 1, q4 = (t & 1) * 4;
#pragma unroll
        for (int i = 0; i < 4; i++) {
            int qq = q4 + i;
            CP16(S0 + QS_OFF + r * 128 + ((qq ^ (r & 7)) << 4), Qg + r * 64 + qq * 8);
        }
    }
    auto load_kv = [&](int jt) {
        uint32_t stK = S0 + KS_OFF + (jt & 1) * 8192;
        uint32_t stV = S0 + VS_OFF + (jt & 1) * 8192;
        int r = t >> 2, q0l = (t & 3) * 2;
        const __half* Kr = Kg + (size_t)(jt * FBN + r) * 64;
        const __half* Vr = Vg + (size_t)(jt * FBN + r) * 64;
#pragma unroll
        for (int i = 0; i < 2; i++) {
            int qq = q0l + i;
            CP16(stK + r * 128 + ((qq ^ (r & 7)) << 4), Kr + qq * 8);
        }
#pragma unroll
        for (int i = 0; i < 2; i++) {
            int qq = q0l + i;
            CP16(stV + r * 128 + ((qq ^ (r & 7)) << 4), Vr + qq * 8);
        }
    };
    load_kv(0); CP_COMMIT();
    load_kv(1); CP_COMMIT();
    CP_WAIT(1);
    __syncthreads();

    const int rx = lane & 7;
    const int r8 = ((lane >> 3) & 1) * 8;
    const int qh = (lane >> 4) & 1;
    const int rB8 = ((lane >> 4) & 1) * 8;
    const int qB  = (lane >> 3) & 1;
    const int g  = lane >> 2, t4 = lane & 3;
    const int row0 = q0 + w * 16 + g;

    uint32_t qf[4][4];
    {
        const uint32_t base = S0 + QS_OFF + (w * 16 + r8 + rx) * 128;
#pragma unroll
        for (int ks = 0; ks < 4; ks++)
            ldsm4(qf[ks], base + (((2 * ks + qh) ^ rx) << 4));
    }

    float o[8][4];
#pragma unroll
    for (int nt = 0; nt < 8; nt++)
#pragma unroll
        for (int i = 0; i < 4; i++) o[nt][i] = 0.0f;
    float mrow[2] = { -1e30f, -1e30f };
    float lrow[2] = { 0.0f, 0.0f };

    const float scL = 0.125f * 1.44269504089f;

    for (int jt = 0; jt < ntiles; jt++) {
        if (jt > 0) {
            CP_WAIT(0);
            __syncthreads();
            if (jt + 1 < ntiles) { load_kv(jt + 1); CP_COMMIT(); }
        }
        const int j0 = jt * FBN;
        if (j0 > q0 + w * 16 + 15) continue;

        const uint32_t stK = S0 + KS_OFF + (jt & 1) * 8192;
        const uint32_t stV = S0 + VS_OFF + (jt & 1) * 8192;

        float s[8][4];
#pragma unroll
        for (int nt = 0; nt < 8; nt++)
#pragma unroll
            for (int i = 0; i < 4; i++) s[nt][i] = 0.0f;

#pragma unroll
        for (int ks = 0; ks < 4; ks++) {
            uint32_t kf[4][4];
            const uint32_t bph = ((2 * ks + qB) ^ rx) << 4;
#pragma unroll
            for (int p = 0; p < 4; p++)
                ldsm4(kf[p], stK + (p * 16 + rB8 + rx) * 128 + bph);
#pragma unroll
            for (int nt = 0; nt < 8; nt++)
                mma_f16(s[nt], qf[ks],
                        kf[nt >> 1][(nt & 1) * 2],
                        kf[nt >> 1][(nt & 1) * 2 + 1]);
        }

        const bool full_ok = (j0 + FBN - 1 <= q0 + w * 16);
        float rmax0 = -1e30f, rmax1 = -1e30f;
#pragma unroll
        for (int nt = 0; nt < 8; nt++) {
            const int c0 = j0 + nt * 8 + 2 * t4;
            s[nt][0] *= scL; s[nt][1] *= scL; s[nt][2] *= scL; s[nt][3] *= scL;
            if (!full_ok) {
                if (c0     > row0)     s[nt][0] = -1e30f;
                if (c0 + 1 > row0)     s[nt][1] = -1e30f;
                if (c0     > row0 + 8) s[nt][2] = -1e30f;
                if (c0 + 1 > row0 + 8) s[nt][3] = -1e30f;
            }
            rmax0 = fmaxf(rmax0, fmaxf(s[nt][0], s[nt][1]));
            rmax1 = fmaxf(rmax1, fmaxf(s[nt][2], s[nt][3]));
        }
        rmax0 = fmaxf(rmax0, __shfl_xor_sync(0xffffffffu, rmax0, 1));
        rmax0 = fmaxf(rmax0, __shfl_xor_sync(0xffffffffu, rmax0, 2));
        rmax1 = fmaxf(rmax1, __shfl_xor_sync(0xffffffffu, rmax1, 1));
        rmax1 = fmaxf(rmax1, __shfl_xor_sync(0xffffffffu, rmax1, 2));

        const float mn0 = fmaxf(mrow[0], rmax0);
        const float mn1 = fmaxf(mrow[1], rmax1);
        const float al0 = ex2(mrow[0] - mn0);
        const float al1 = ex2(mrow[1] - mn1);
        float rs0 = 0.0f, rs1 = 0.0f;
#pragma unroll
        for (int nt = 0; nt < 8; nt++) {
            s[nt][0] = ex2(s[nt][0] - mn0);
            s[nt][1] = ex2(s[nt][1] - mn0);
            s[nt][2] = ex2(s[nt][2] - mn1);
            s[nt][3] = ex2(s[nt][3] - mn1);
            rs0 += s[nt][0] + s[nt][1];
            rs1 += s[nt][2] + s[nt][3];
        }
        rs0 += __shfl_xor_sync(0xffffffffu, rs0, 1);
        rs0 += __shfl_xor_sync(0xffffffffu, rs0, 2);
        rs1 += __shfl_xor_sync(0xffffffffu, rs1, 1);
        rs1 += __shfl_xor_sync(0xffffffffu, rs1, 2);
        lrow[0] = lrow[0] * al0 + rs0;  mrow[0] = mn0;
        lrow[1] = lrow[1] * al1 + rs1;  mrow[1] = mn1;
#pragma unroll
        for (int nt = 0; nt < 8; nt++) {
            o[nt][0] *= al0; o[nt][1] *= al0;
            o[nt][2] *= al1; o[nt][3] *= al1;
        }

#pragma unroll
        for (int ks2 = 0; ks2 < 4; ks2++) {
            uint32_t pf[4];
            pf[0] = pack_h2(s[2 * ks2][0],     s[2 * ks2][1]);
            pf[1] = pack_h2(s[2 * ks2][2],     s[2 * ks2][3]);
            pf[2] = pack_h2(s[2 * ks2 + 1][0], s[2 * ks2 + 1][1]);
            pf[3] = pack_h2(s[2 * ks2 + 1][2], s[2 * ks2 + 1][3]);
#pragma unroll
            for (int p = 0; p < 4; p++) {
                uint32_t vf[4];
                ldsm4t(vf, stV + (16 * ks2 + r8 + rx) * 128 +
                           (((2 * p + qh) ^ rx) << 4));
                mma_f16(o[2 * p],     pf, vf[0], vf[1]);
                mma_f16(o[2 * p + 1], pf, vf[2], vf[3]);
            }
        }
    }

    const int b = bh >> 4, h = bh & 15;
    const float inv0 = 1.0f / lrow[0];
    const float inv1 = 1.0f / lrow[1];
#pragma unroll
    for (int nt = 0; nt < 8; nt++) {
        const int col = h * 64 + nt * 8 + 2 * t4;
        *(__half2*)&g_oh[(size_t)(b * SS + row0) * DD + col] =
            __floats2half2_rn(o[nt][0] * inv0, o[nt][1] * inv0);
        *(__half2*)&g_oh[(size_t)(b * SS + row0 + 8) * DD + col] =
            __floats2half2_rn(o[nt][2] * inv1, o[nt][3] * inv1);
    }
}

// ---------------------------------------------------------------------------
extern "C" void kernel_launch(void* const* d_in, const int* in_sizes, int n_in,
                              void* d_out, int out_size)
{
    const float* x      = (const float*)d_in[0];
    // d_in[1] = mask (causal tril; structure exploited directly)
    const float* w_qkv  = (const float*)d_in[2];
    const float* b_qkv  = (const float*)d_in[3];
    const float* w_o    = (const float*)d_in[4];
    const float* b_o    = (const float*)d_in[5];
    float* out          = (float*)d_out;

    (void)in_sizes; (void)n_in; (void)out_size;

    cudaFuncSetAttribute(gemm_mma<0>, cudaFuncAttributeMaxDynamicSharedMemorySize, GEMM_SMEM);
    cudaFuncSetAttribute(gemm_mma<1>, cudaFuncAttributeMaxDynamicSharedMemorySize, GEMM_SMEM);
    cudaFuncSetAttribute(flash_mma_kernel, cudaFuncAttributeMaxDynamicSharedMemorySize, FLASH_SMEM);

    // fused pre-convert of all fp32 MMA inputs to fp16
    to_half_all<<<XB + WB + OB, 256>>>(x, w_qkv, w_o);

    dim3 g1(N3 / 256, NTOK / 128);       // 12 x 32
    gemm_mma<0><<<g1, 256, GEMM_SMEM>>>(b_qkv, nullptr);

    dim3 g2(SS / FBM, BB * HH);          // 16 x 32
    flash_mma_kernel<<<g2, 256, FLASH_SMEM>>>();

    dim3 g3(DD / 256, NTOK / 128);       // 4 x 32
    gemm_mma<1><<<g3, 256, GEMM_SMEM>>>(b_o, out);
}

// round 16
// speedup vs baseline: 1.0203x; 1.0203x over previous
#include <cuda_runtime.h>
#include <cuda_fp16.h>
#include <cstdint>

// Problem constants
#define BB   2
#define SS   2048
#define DD   1024
#define HH   16
#define DK   64
#define N3   3072   // 3*D
#define NTOK 4096   // B*S

// Scratch (allocation-free rule: __device__ globals) — all fp16 MMA operands
__device__ __half g_qh[BB * HH * SS * DK];   // [bh, s, dk]
__device__ __half g_kh[BB * HH * SS * DK];
__device__ __half g_vh[BB * HH * SS * DK];
__device__ __half g_oh[NTOK * DD];           // [token, h*64+d]
__device__ __half g_xh[NTOK * DD];           // x -> fp16
__device__ __half g_wqkvh[N3 * DD];          // w_qkv -> fp16
__device__ __half g_woh[DD * DD];            // w_o -> fp16

// ---------------------------------------------------------------------------
// PTX helpers — base sm_80/sm_90 ISA only (harness targets plain sm_103)
// ---------------------------------------------------------------------------
__device__ __forceinline__ uint32_t smem_u32(const void* p) {
    uint32_t a;
    asm("{ .reg .u64 t; cvta.to.shared.u64 t, %1; cvt.u32.u64 %0, t; }"
        : "=r"(a) : "l"(p));
    return a;
}

#define CP16(dst, src) \
    asm volatile("cp.async.cg.shared.global [%0], [%1], 16;" :: "r"(dst), "l"(src))
#define CP_COMMIT() asm volatile("cp.async.commit_group;" ::: "memory")
#define CP_WAIT(n)  asm volatile("cp.async.wait_group %0;" :: "n"(n) : "memory")

__device__ __forceinline__ void ldsm4(uint32_t* r, uint32_t addr) {
    asm volatile("ldmatrix.sync.aligned.m8n8.x4.shared.b16 {%0,%1,%2,%3}, [%4];"
        : "=r"(r[0]), "=r"(r[1]), "=r"(r[2]), "=r"(r[3]) : "r"(addr));
}
__device__ __forceinline__ void ldsm4t(uint32_t* r, uint32_t addr) {
    asm volatile("ldmatrix.sync.aligned.m8n8.x4.trans.shared.b16 {%0,%1,%2,%3}, [%4];"
        : "=r"(r[0]), "=r"(r[1]), "=r"(r[2]), "=r"(r[3]) : "r"(addr));
}

__device__ __forceinline__ void mma_f16(float* c, const uint32_t* a,
                                        uint32_t b0, uint32_t b1) {
    asm volatile(
        "mma.sync.aligned.m16n8k16.row.col.f32.f16.f16.f32 "
        "{%0,%1,%2,%3}, {%4,%5,%6,%7}, {%8,%9}, {%0,%1,%2,%3};"
        : "+f"(c[0]), "+f"(c[1]), "+f"(c[2]), "+f"(c[3])
        : "r"(a[0]), "r"(a[1]), "r"(a[2]), "r"(a[3]), "r"(b0), "r"(b1));
}

__device__ __forceinline__ float ex2(float x) {
    float r;
    asm("ex2.approx.f32 %0, %1;" : "=f"(r) : "f"(x));
    return r;
}
__device__ __forceinline__ uint32_t pack_h2(float a, float b) {
    __half2 h = __floats2half2_rn(a, b);
    return *(uint32_t*)&h;
}

// ---------------------------------------------------------------------------
// Kernel 0: fused fp32 -> fp16 convert, 8 floats/thread, 16B stores
// ---------------------------------------------------------------------------
#define XB  (NTOK * DD / 2048)   // 2048 blocks
#define WB  (N3 * DD / 2048)     // 1536 blocks
#define OB  (DD * DD / 2048)     // 512 blocks

__global__ __launch_bounds__(256) void to_half_all(
    const float* __restrict__ x, const float* __restrict__ wqkv,
    const float* __restrict__ wo)
{
    int b = blockIdx.x;
    const float* src;  uint4* dst;
    if (b < XB)            { src = x;    dst = (uint4*)g_xh; }
    else if (b < XB + WB)  { src = wqkv; dst = (uint4*)g_wqkvh; b -= XB; }
    else                   { src = wo;   dst = (uint4*)g_woh;   b -= XB + WB; }
    const int i = b * 256 + threadIdx.x;       // 8-float group index
    float4 v0 = *(const float4*)(src + i * 8);
    float4 v1 = *(const float4*)(src + i * 8 + 4);
    uint4 o;
    o.x = pack_h2(v0.x, v0.y); o.y = pack_h2(v0.z, v0.w);
    o.z = pack_h2(v1.x, v1.y); o.w = pack_h2(v1.z, v1.w);
    dst[i] = o;
}

// ---------------------------------------------------------------------------
// fp16 mma.sync GEMM (proven round-10 version) + PDL
// Block tile 128x128, 8 warps (64x32), 3-stage cp.async, 2 CTA/SM.
// ---------------------------------------------------------------------------
#define STAGES      3
#define STAGE_BYTES 32768
#define NCHUNK      16
#define GEMM_SMEM   (1024 + STAGES * STAGE_BYTES)

template<int MODE>
__global__ __launch_bounds__(256, 2) void gemm_mma(
    const float* __restrict__ bias, float* __restrict__ Out)
{
    extern __shared__ __align__(16) char smem_raw[];
    const uint32_t sb  = smem_u32(smem_raw);
    const uint32_t st0 = (sb + 1023u) & ~1023u;

    const int t    = threadIdx.x;
    const int lane = t & 31;
    const int wid  = t >> 5;
    const int wm   = wid & 1;
    const int wn   = wid >> 1;
    const int m0   = blockIdx.y * 128;
    const int n0   = blockIdx.x * 128;

    // PDL: wait for producer grid's writes before first global read
    cudaGridDependencySynchronize();

    const __half* A  = (MODE == 1) ? g_oh : g_xh;
    const __half* Bw = (MODE == 1) ? g_woh : g_wqkvh;

    const int rb = t >> 3;
    const int q  = t & 7;
    const __half* Abase = A  + (size_t)m0 * DD + q * 8;
    const __half* Bbase = Bw + (size_t)n0 * DD + q * 8;

    auto load_chunk = [&](int c) {
        const uint32_t st = st0 + (c % STAGES) * STAGE_BYTES;
        const __half* Ac = Abase + c * 64;
        const __half* Bc = Bbase + c * 64;
#pragma unroll
        for (int it = 0; it < 4; it++) {
            int r = rb + it * 32;
            CP16(st + r * 128 + ((q ^ (r & 7)) << 4), Ac + (size_t)r * DD);
        }
#pragma unroll
        for (int it = 0; it < 4; it++) {
            int r = rb + it * 32;
            CP16(st + 16384 + r * 128 + ((q ^ (r & 7)) << 4), Bc + (size_t)r * DD);
        }
    };

    const int rx = lane & 7;
    const int r8 = ((lane >> 3) & 1) * 8;
    const int qh = (lane >> 4) & 1;
    const int rB8 = ((lane >> 4) & 1) * 8;
    const int qB  = (lane >> 3) & 1;

    float acc[4][4][4];
#pragma unroll
    for (int mt = 0; mt < 4; mt++)
#pragma unroll
        for (int nt = 0; nt < 4; nt++)
#pragma unroll
            for (int i = 0; i < 4; i++) acc[mt][nt][i] = 0.0f;

    load_chunk(0); CP_COMMIT();
    load_chunk(1); CP_COMMIT();

    for (int c = 0; c < NCHUNK; c++) {
        CP_WAIT(1);
        __syncthreads();

        if (c + 2 < NCHUNK) load_chunk(c + 2);
        CP_COMMIT();

        const uint32_t stA = st0 + (c % STAGES) * STAGE_BYTES;
        const uint32_t stB = stA + 16384;
#pragma unroll
        for (int ks = 0; ks < 4; ks++) {
            uint32_t a[4][4], b[2][4];
            const uint32_t aph = ((2 * ks + qh) ^ rx) << 4;
            const uint32_t bph = ((2 * ks + qB) ^ rx) << 4;
#pragma unroll
            for (int mt = 0; mt < 4; mt++)
                ldsm4(a[mt], stA + (wm * 64 + mt * 16 + r8 + rx) * 128 + aph);
#pragma unroll
            for (int p = 0; p < 2; p++)
                ldsm4(b[p], stB + (wn * 32 + p * 16 + rB8 + rx) * 128 + bph);
#pragma unroll
            for (int mt = 0; mt < 4; mt++)
#pragma unroll
                for (int nt = 0; nt < 4; nt++)
                    mma_f16(acc[mt][nt], a[mt],
                            b[nt >> 1][(nt & 1) * 2],
                            b[nt >> 1][(nt & 1) * 2 + 1]);
        }
    }

    // PDL: mainloop done — let the dependent grid start launching
    cudaTriggerProgrammaticLaunchCompletion();

    const int g  = lane >> 2;
    const int t4 = lane & 3;
#pragma unroll
    for (int mt = 0; mt < 4; mt++) {
        const int m = m0 + wm * 64 + mt * 16 + g;
#pragma unroll
        for (int nt = 0; nt < 4; nt++) {
            const int n = n0 + wn * 32 + nt * 8 + 2 * t4;
            const float2 b2 = *(const float2*)&bias[n];
            float2 v0, v1;
            v0.x = acc[mt][nt][0] + b2.x; v0.y = acc[mt][nt][1] + b2.y;
            v1.x = acc[mt][nt][2] + b2.x; v1.y = acc[mt][nt][3] + b2.y;
            if (MODE == 1) {
                *(float2*)&Out[(size_t)m * DD + n]       = v0;
                *(float2*)&Out[(size_t)(m + 8) * DD + n] = v1;
            } else {
                const __half2 h0 = __floats2half2_rn(v0.x, v0.y);
                const __half2 h1 = __floats2half2_rn(v1.x, v1.y);
                const int sel = n >> 10;
                const int h   = (n & 1023) >> 6;
                const int dk  = n & 63;
                __half* dst = (sel == 0) ? g_qh : ((sel == 1) ? g_kh : g_vh);
                const int b0i = m >> 11, s0 = m & 2047;
                *(__half2*)&dst[((size_t)(b0i * HH + h) * SS + s0) * DK + dk] = h0;
                const int b1i = (m + 8) >> 11, s1 = (m + 8) & 2047;
                *(__half2*)&dst[((size_t)(b1i * HH + h) * SS + s1) * DK + dk] = h1;
            }
        }
    }
}

// ---------------------------------------------------------------------------
// Kernel 2: flash attention (proven round-10 version) + PDL
// ---------------------------------------------------------------------------
#define FBM 128
#define FBN 64
#define QS_OFF  0
#define KS_OFF  16384
#define VS_OFF  32768
#define FLASH_SMEM 49152

__global__ __launch_bounds__(256) void flash_mma_kernel()
{
    extern __shared__ __align__(16) char sm[];
    const uint32_t S0 = smem_u32(sm);

    const int t    = threadIdx.x;
    const int lane = t & 31;
    const int w    = t >> 5;
    const int bh   = blockIdx.y;
    const int qt   = (int)gridDim.x - 1 - (int)blockIdx.x;   // heavy first
    const int q0   = qt * FBM;

    // PDL: Q/K/V produced by gemm0
    cudaGridDependencySynchronize();

    const __half* Qg = g_qh + (size_t)(bh * SS + q0) * DK;
    const __half* Kg = g_kh + (size_t)bh * SS * DK;
    const __half* Vg = g_vh + (size_t)bh * SS * DK;

    const int ntiles = q0 / FBN + 2;

    {
        int r = t >> 1, q4 = (t & 1) * 4;
#pragma unroll
        for (int i = 0; i < 4; i++) {
            int qq = q4 + i;
            CP16(S0 + QS_OFF + r * 128 + ((qq ^ (r & 7)) << 4), Qg + r * 64 + qq * 8);
        }
    }
    auto load_kv = [&](int jt) {
        uint32_t stK = S0 + KS_OFF + (jt & 1) * 8192;
        uint32_t stV = S0 + VS_OFF + (jt & 1) * 8192;
        int r = t >> 2, q0l = (t & 3) * 2;
        const __half* Kr = Kg + (size_t)(jt * FBN + r) * 64;
        const __half* Vr = Vg + (size_t)(jt * FBN + r) * 64;
#pragma unroll
        for (int i = 0; i < 2; i++) {
            int qq = q0l + i;
            CP16(stK + r * 128 + ((qq ^ (r & 7)) << 4), Kr + qq * 8);
        }
#pragma unroll
        for (int i = 0; i < 2; i++) {
            int qq = q0l + i;
            CP16(stV + r * 128 + ((qq ^ (r & 7)) << 4), Vr + qq * 8);
        }
    };
    load_kv(0); CP_COMMIT();
    load_kv(1); CP_COMMIT();
    CP_WAIT(1);
    __syncthreads();

    const int rx = lane & 7;
    const int r8 = ((lane >> 3) & 1) * 8;
    const int qh = (lane >> 4) & 1;
    const int rB8 = ((lane >> 4) & 1) * 8;
    const int qB  = (lane >> 3) & 1;
    const int g  = lane >> 2, t4 = lane & 3;
    const int row0 = q0 + w * 16 + g;

    uint32_t qf[4][4];
    {
        const uint32_t base = S0 + QS_OFF + (w * 16 + r8 + rx) * 128;
#pragma unroll
        for (int ks = 0; ks < 4; ks++)
            ldsm4(qf[ks], base + (((2 * ks + qh) ^ rx) << 4));
    }

    float o[8][4];
#pragma unroll
    for (int nt = 0; nt < 8; nt++)
#pragma unroll
        for (int i = 0; i < 4; i++) o[nt][i] = 0.0f;
    float mrow[2] = { -1e30f, -1e30f };
    float lrow[2] = { 0.0f, 0.0f };

    const float scL = 0.125f * 1.44269504089f;

    for (int jt = 0; jt < ntiles; jt++) {
        if (jt > 0) {
            CP_WAIT(0);
            __syncthreads();
            if (jt + 1 < ntiles) { load_kv(jt + 1); CP_COMMIT(); }
        }
        const int j0 = jt * FBN;
        if (j0 > q0 + w * 16 + 15) continue;

        const uint32_t stK = S0 + KS_OFF + (jt & 1) * 8192;
        const uint32_t stV = S0 + VS_OFF + (jt & 1) * 8192;

        float s[8][4];
#pragma unroll
        for (int nt = 0; nt < 8; nt++)
#pragma unroll
            for (int i = 0; i < 4; i++) s[nt][i] = 0.0f;

#pragma unroll
        for (int ks = 0; ks < 4; ks++) {
            uint32_t kf[4][4];
            const uint32_t bph = ((2 * ks + qB) ^ rx) << 4;
#pragma unroll
            for (int p = 0; p < 4; p++)
                ldsm4(kf[p], stK + (p * 16 + rB8 + rx) * 128 + bph);
#pragma unroll
            for (int nt = 0; nt < 8; nt++)
                mma_f16(s[nt], qf[ks],
                        kf[nt >> 1][(nt & 1) * 2],
                        kf[nt >> 1][(nt & 1) * 2 + 1]);
        }

        const bool full_ok = (j0 + FBN - 1 <= q0 + w * 16);
        float rmax0 = -1e30f, rmax1 = -1e30f;
#pragma unroll
        for (int nt = 0; nt < 8; nt++) {
            const int c0 = j0 + nt * 8 + 2 * t4;
            s[nt][0] *= scL; s[nt][1] *= scL; s[nt][2] *= scL; s[nt][3] *= scL;
            if (!full_ok) {
                if (c0     > row0)     s[nt][0] = -1e30f;
                if (c0 + 1 > row0)     s[nt][1] = -1e30f;
                if (c0     > row0 + 8) s[nt][2] = -1e30f;
                if (c0 + 1 > row0 + 8) s[nt][3] = -1e30f;
            }
            rmax0 = fmaxf(rmax0, fmaxf(s[nt][0], s[nt][1]));
            rmax1 = fmaxf(rmax1, fmaxf(s[nt][2], s[nt][3]));
        }
        rmax0 = fmaxf(rmax0, __shfl_xor_sync(0xffffffffu, rmax0, 1));
        rmax0 = fmaxf(rmax0, __shfl_xor_sync(0xffffffffu, rmax0, 2));
        rmax1 = fmaxf(rmax1, __shfl_xor_sync(0xffffffffu, rmax1, 1));
        rmax1 = fmaxf(rmax1, __shfl_xor_sync(0xffffffffu, rmax1, 2));

        const float mn0 = fmaxf(mrow[0], rmax0);
        const float mn1 = fmaxf(mrow[1], rmax1);
        const float al0 = ex2(mrow[0] - mn0);
        const float al1 = ex2(mrow[1] - mn1);
        float rs0 = 0.0f, rs1 = 0.0f;
#pragma unroll
        for (int nt = 0; nt < 8; nt++) {
            s[nt][0] = ex2(s[nt][0] - mn0);
            s[nt][1] = ex2(s[nt][1] - mn0);
            s[nt][2] = ex2(s[nt][2] - mn1);
            s[nt][3] = ex2(s[nt][3] - mn1);
            rs0 += s[nt][0] + s[nt][1];
            rs1 += s[nt][2] + s[nt][3];
        }
        rs0 += __shfl_xor_sync(0xffffffffu, rs0, 1);
        rs0 += __shfl_xor_sync(0xffffffffu, rs0, 2);
        rs1 += __shfl_xor_sync(0xffffffffu, rs1, 1);
        rs1 += __shfl_xor_sync(0xffffffffu, rs1, 2);
        lrow[0] = lrow[0] * al0 + rs0;  mrow[0] = mn0;
        lrow[1] = lrow[1] * al1 + rs1;  mrow[1] = mn1;
#pragma unroll
        for (int nt = 0; nt < 8; nt++) {
            o[nt][0] *= al0; o[nt][1] *= al0;
            o[nt][2] *= al1; o[nt][3] *= al1;
        }

#pragma unroll
        for (int ks2 = 0; ks2 < 4; ks2++) {
            uint32_t pf[4];
            pf[0] = pack_h2(s[2 * ks2][0],     s[2 * ks2][1]);
            pf[1] = pack_h2(s[2 * ks2][2],     s[2 * ks2][3]);
            pf[2] = pack_h2(s[2 * ks2 + 1][0], s[2 * ks2 + 1][1]);
            pf[3] = pack_h2(s[2 * ks2 + 1][2], s[2 * ks2 + 1][3]);
#pragma unroll
            for (int p = 0; p < 4; p++) {
                uint32_t vf[4];
                ldsm4t(vf, stV + (16 * ks2 + r8 + rx) * 128 +
                           (((2 * p + qh) ^ rx) << 4));
                mma_f16(o[2 * p],     pf, vf[0], vf[1]);
                mma_f16(o[2 * p + 1], pf, vf[2], vf[3]);
            }
        }
    }

    // PDL: mainloop done — let oproj start launching
    cudaTriggerProgrammaticLaunchCompletion();

    const int b = bh >> 4, h = bh & 15;
    const float inv0 = 1.0f / lrow[0];
    const float inv1 = 1.0f / lrow[1];
#pragma unroll
    for (int nt = 0; nt < 8; nt++) {
        const int col = h * 64 + nt * 8 + 2 * t4;
        *(__half2*)&g_oh[(size_t)(b * SS + row0) * DD + col] =
            __floats2half2_rn(o[nt][0] * inv0, o[nt][1] * inv0);
        *(__half2*)&g_oh[(size_t)(b * SS + row0 + 8) * DD + col] =
            __floats2half2_rn(o[nt][2] * inv1, o[nt][3] * inv1);
    }
}

// ---------------------------------------------------------------------------
extern "C" void kernel_launch(void* const* d_in, const int* in_sizes, int n_in,
                              void* d_out, int out_size)
{
    const float* x      = (const float*)d_in[0];
    // d_in[1] = mask (causal tril; structure exploited directly)
    const float* w_qkv  = (const float*)d_in[2];
    const float* b_qkv  = (const float*)d_in[3];
    const float* w_o    = (const float*)d_in[4];
    const float* b_o    = (const float*)d_in[5];
    float* out          = (float*)d_out;

    (void)in_sizes; (void)n_in; (void)out_size;

    cudaFuncSetAttribute(gemm_mma<0>, cudaFuncAttributeMaxDynamicSharedMemorySize, GEMM_SMEM);
    cudaFuncSetAttribute(gemm_mma<1>, cudaFuncAttributeMaxDynamicSharedMemorySize, GEMM_SMEM);
    cudaFuncSetAttribute(flash_mma_kernel, cudaFuncAttributeMaxDynamicSharedMemorySize, FLASH_SMEM);

    // fused pre-convert of all fp32 MMA inputs to fp16
    to_half_all<<<XB + WB + OB, 256>>>(x, w_qkv, w_o);

    // PDL launch attribute (consumers may begin launching during producer tail)
    cudaLaunchAttribute pdl[1];
    pdl[0].id = cudaLaunchAttributeProgrammaticStreamSerialization;
    pdl[0].val.programmaticStreamSerializationAllowed = 1;

    {   // gemm0: QKV projection
        cudaLaunchConfig_t cfg = {};
        cfg.gridDim = dim3(N3 / 128, NTOK / 128);
        cfg.blockDim = dim3(256);
        cfg.dynamicSmemBytes = GEMM_SMEM;
        cfg.stream = 0;
        cfg.attrs = pdl; cfg.numAttrs = 1;
        cudaLaunchKernelEx(&cfg, gemm_mma<0>, b_qkv, (float*)nullptr);
    }
    {   // flash attention
        cudaLaunchConfig_t cfg = {};
        cfg.gridDim = dim3(SS / FBM, BB * HH);
        cfg.blockDim = dim3(256);
        cfg.dynamicSmemBytes = FLASH_SMEM;
        cfg.stream = 0;
        cfg.attrs = pdl; cfg.numAttrs = 1;
        cudaLaunchKernelEx(&cfg, flash_mma_kernel);
    }
    {   // output projection
        cudaLaunchConfig_t cfg = {};
        cfg.gridDim = dim3(DD / 128, NTOK / 128);
        cfg.blockDim = dim3(256);
        cfg.dynamicSmemBytes = GEMM_SMEM;
        cfg.stream = 0;
        cfg.attrs = pdl; cfg.numAttrs = 1;
        cudaLaunchKernelEx(&cfg, gemm_mma<1>, b_o, out);
    }
}